// round 2
// baseline (speedup 1.0000x reference)
#include <cuda_runtime.h>
#include <math.h>

// Problem constants
#define Bsz 512
#define Tsz 128
#define Hsz 512
#define Vsz 512
#define G4  (4*Hsz)   // 2048

// ---------------- device scratch (static allocation, allowed) ----------------
__device__ float g_seq0[Bsz*Tsz*Hsz];   // 134 MB : inp, later layer-2 output
__device__ float g_seq1[Bsz*Tsz*Hsz];   // 134 MB : layer-1 output
__device__ float g_xg[Bsz*Tsz*G4];      // 536 MB : precomputed input gates per layer
__device__ float g_hbuf0[Bsz*Hsz];      // ping
__device__ float g_hbuf1[Bsz*Hsz];      // pong
__device__ float g_cst[Bsz*Hsz];        // cell state

// ---------------- embed + condition ----------------
// inp[b,t,h] = emb[trg[b,t],h] + y[b]*yW[h] + yb[h];  trg = [V, x[:, :-1]]
__global__ void embed_kernel(const int* __restrict__ x, const float* __restrict__ y,
                             const float* __restrict__ emb, const float* __restrict__ yW,
                             const float* __restrict__ yb, float* __restrict__ out)
{
    int bt = blockIdx.x;            // 0..B*T-1
    int b = bt / Tsz, t = bt % Tsz;
    int h = threadIdx.x;            // H = 512 threads
    int tok = (t == 0) ? Vsz : x[b*Tsz + (t-1)];
    out[(size_t)bt*Hsz + h] = emb[(size_t)tok*Hsz + h] + y[b]*yW[h] + yb[h];
}

__global__ void zero2_kernel(float* a, float* b, int n)
{
    int i = blockIdx.x*blockDim.x + threadIdx.x;
    if (i < n) { a[i] = 0.f; b[i] = 0.f; }
}

// ---------------- generic fp32 GEMM: C[M,N] = A[M,K] * W[N,K]^T + b1 (+b2) ----
// BM=128, BN=128, BK=16, 256 threads, 8x8 micro-tile per thread.
#define BM 128
#define BN 128
#define BKg 16
__global__ __launch_bounds__(256)
void gemm_bias(const float* __restrict__ A, const float* __restrict__ W,
               const float* __restrict__ b1, const float* __restrict__ b2,
               float* __restrict__ C, int M, int N, int K)
{
    __shared__ float As[BKg][BM];
    __shared__ float Bs[BKg][BN];
    int tid = threadIdx.x;
    int tx = tid & 15, ty = tid >> 4;
    int row0 = blockIdx.y * BM;
    int col0 = blockIdx.x * BN;

    float acc[8][8];
#pragma unroll
    for (int i = 0; i < 8; i++)
#pragma unroll
        for (int j = 0; j < 8; j++) acc[i][j] = 0.f;

    for (int k0 = 0; k0 < K; k0 += BKg) {
#pragma unroll
        for (int i = 0; i < 2; i++) {
            int idx = tid + i*256;          // 0..511
            int r  = idx >> 2;              // 0..127
            int kq = (idx & 3) << 2;        // 0,4,8,12
            float4 v = *(const float4*)(A + (size_t)(row0 + r)*K + k0 + kq);
            As[kq+0][r] = v.x; As[kq+1][r] = v.y; As[kq+2][r] = v.z; As[kq+3][r] = v.w;
            float4 w = *(const float4*)(W + (size_t)(col0 + r)*K + k0 + kq);
            Bs[kq+0][r] = w.x; Bs[kq+1][r] = w.y; Bs[kq+2][r] = w.z; Bs[kq+3][r] = w.w;
        }
        __syncthreads();
#pragma unroll
        for (int kk = 0; kk < BKg; kk++) {
            float a[8], bb[8];
            *(float4*)(a)    = *(const float4*)&As[kk][ty*8];
            *(float4*)(a+4)  = *(const float4*)&As[kk][ty*8+4];
            *(float4*)(bb)   = *(const float4*)&Bs[kk][tx*8];
            *(float4*)(bb+4) = *(const float4*)&Bs[kk][tx*8+4];
#pragma unroll
            for (int i = 0; i < 8; i++)
#pragma unroll
                for (int j = 0; j < 8; j++) acc[i][j] += a[i]*bb[j];
        }
        __syncthreads();
    }

    float bv[8];
#pragma unroll
    for (int j = 0; j < 8; j++) {
        int c = col0 + tx*8 + j;
        float v = b1 ? b1[c] : 0.f;
        if (b2) v += b2[c];
        bv[j] = v;
    }
#pragma unroll
    for (int i = 0; i < 8; i++) {
        size_t off = (size_t)(row0 + ty*8 + i)*N + col0 + tx*8;
        float4 o0, o1;
        o0.x = acc[i][0]+bv[0]; o0.y = acc[i][1]+bv[1];
        o0.z = acc[i][2]+bv[2]; o0.w = acc[i][3]+bv[3];
        o1.x = acc[i][4]+bv[4]; o1.y = acc[i][5]+bv[5];
        o1.z = acc[i][6]+bv[6]; o1.w = acc[i][7]+bv[7];
        *(float4*)(C + off)     = o0;
        *(float4*)(C + off + 4) = o1;
    }
}

// ---------------- fused LSTM step: g = xg_t + h_prev*Whh^T ; gates ; state ---
// Tile: 64 batch rows x 16 u-columns x 4 gates. 256 threads (16x16),
// each thread: 4 batch rows x 1 u x 4 gates = 16 accumulators.
#define TB 64
#define TU 16
#define BKs 32
__global__ __launch_bounds__(256)
void lstm_step(const float* __restrict__ xg, const float* __restrict__ Wh,
               const float* __restrict__ hin, float* __restrict__ hout,
               float* __restrict__ cst, float* __restrict__ seq_out, int t)
{
    __shared__ float Hs[BKs][TB];   // h_prev tile, transposed
    __shared__ float Ws[BKs][64];   // Whh rows: col = gate*16 + u_local
    int tid = threadIdx.x;
    int tx = tid & 15, ty = tid >> 4;
    int u0 = blockIdx.x * TU;
    int b0 = blockIdx.y * TB;

    float acc[4][4];                // [b_sub][gate]
#pragma unroll
    for (int i = 0; i < 4; i++)
#pragma unroll
        for (int g = 0; g < 4; g++) acc[i][g] = 0.f;

    for (int k0 = 0; k0 < Hsz; k0 += BKs) {
#pragma unroll
        for (int i = 0; i < 2; i++) {
            int idx = tid + i*256;          // 0..511
            int r  = idx >> 3;              // 0..63
            int kq = (idx & 7) << 2;        // 0..28
            float4 v = *(const float4*)(hin + (size_t)(b0 + r)*Hsz + k0 + kq);
            Hs[kq+0][r] = v.x; Hs[kq+1][r] = v.y; Hs[kq+2][r] = v.z; Hs[kq+3][r] = v.w;
            int gi = r >> 4, ul = r & 15;   // gate / u_local
            float4 w = *(const float4*)(Wh + (size_t)(gi*Hsz + u0 + ul)*Hsz + k0 + kq);
            Ws[kq+0][r] = w.x; Ws[kq+1][r] = w.y; Ws[kq+2][r] = w.z; Ws[kq+3][r] = w.w;
        }
        __syncthreads();
#pragma unroll
        for (int kk = 0; kk < BKs; kk++) {
            float a[4];
            *(float4*)a = *(const float4*)&Hs[kk][ty*4];
            float w0 = Ws[kk][tx], w1 = Ws[kk][16+tx],
                  w2 = Ws[kk][32+tx], w3 = Ws[kk][48+tx];
#pragma unroll
            for (int i = 0; i < 4; i++) {
                acc[i][0] += a[i]*w0;
                acc[i][1] += a[i]*w1;
                acc[i][2] += a[i]*w2;
                acc[i][3] += a[i]*w3;
            }
        }
        __syncthreads();
    }

    int u = u0 + tx;
#pragma unroll
    for (int i = 0; i < 4; i++) {
        int b = b0 + ty*4 + i;
        size_t xoff = ((size_t)b*Tsz + t)*G4 + u;
        float gi = acc[i][0] + xg[xoff];
        float gf = acc[i][1] + xg[xoff + Hsz];
        float gg = acc[i][2] + xg[xoff + 2*Hsz];
        float go = acc[i][3] + xg[xoff + 3*Hsz];
        float ig = 1.f/(1.f + expf(-gi));
        float fg = 1.f/(1.f + expf(-gf));
        float og = 1.f/(1.f + expf(-go));
        float gt = tanhf(gg);
        int so = b*Hsz + u;
        float cN = fg * cst[so] + ig * gt;
        cst[so] = cN;
        float hN = og * tanhf(cN);
        hout[so] = hN;
        seq_out[((size_t)b*Tsz + t)*Hsz + u] = hN;
    }
}

// ---------------- launch ----------------
extern "C" void kernel_launch(void* const* d_in, const int* in_sizes, int n_in,
                              void* d_out, int out_size)
{
    const int*   x    = (const int*)  d_in[0];
    const float* y    = (const float*)d_in[1];
    const float* emb  = (const float*)d_in[2];
    const float* yW   = (const float*)d_in[3];
    const float* yb   = (const float*)d_in[4];
    const float* Wih  = (const float*)d_in[5];
    const float* Whh  = (const float*)d_in[6];
    const float* bih  = (const float*)d_in[7];
    const float* bhh  = (const float*)d_in[8];
    const float* decW = (const float*)d_in[9];
    const float* decb = (const float*)d_in[10];
    float* out = (float*)d_out;

    float *seq0, *seq1, *xg, *h0, *h1, *c;
    cudaGetSymbolAddress((void**)&seq0, g_seq0);
    cudaGetSymbolAddress((void**)&seq1, g_seq1);
    cudaGetSymbolAddress((void**)&xg,   g_xg);
    cudaGetSymbolAddress((void**)&h0,   g_hbuf0);
    cudaGetSymbolAddress((void**)&h1,   g_hbuf1);
    cudaGetSymbolAddress((void**)&c,    g_cst);
    float* hb[2] = { h0, h1 };

    const int MT = Bsz*Tsz;   // 65536

    // 1. embed + condition -> seq0
    embed_kernel<<<MT, Hsz>>>(x, y, emb, yW, yb, seq0);

    // 2. two LSTM layers
    const float* in_seq  = seq0;
    float*       out_seq = seq1;
    for (int l = 0; l < 2; l++) {
        const float* Wi = Wih + (size_t)l*G4*Hsz;
        const float* Wr = Whh + (size_t)l*G4*Hsz;
        const float* bi = bih + (size_t)l*G4;
        const float* bh = bhh + (size_t)l*G4;

        // xg = in_seq @ Wi^T + bi + bh
        gemm_bias<<<dim3(G4/BN, MT/BM), 256>>>(in_seq, Wi, bi, bh, xg, MT, G4, Hsz);

        // reset state
        zero2_kernel<<<(Bsz*Hsz + 255)/256, 256>>>(hb[0], c, Bsz*Hsz);

        // sequential recurrence, double-buffered h
        for (int t = 0; t < Tsz; t++) {
            lstm_step<<<dim3(Hsz/TU, Bsz/TB), 256>>>(
                xg, Wr, hb[t & 1], hb[(t + 1) & 1], c, out_seq, t);
        }

        // swap sequence buffers for next layer
        const float* tmp_in = out_seq;
        out_seq = (float*)in_seq;
        in_seq  = tmp_in;
    }

    // 3. decoder: logits = h_seq @ decW^T + decb   (h_seq is in in_seq now)
    gemm_bias<<<dim3(Vsz/BN, MT/BM), 256>>>(in_seq, decW, decb, nullptr, out, MT, Vsz, Hsz);
}

// round 4
// speedup vs baseline: 1.8286x; 1.8286x over previous
#include <cuda_runtime.h>
#include <cuda_bf16.h>
#include <stdint.h>
#include <math.h>

#define Bsz 512
#define Tsz 128
#define Hsz 512
#define Vsz 512
#define NBT 65536
#define G4  2048
typedef __nv_bfloat16 bf16;

// ---------------- device scratch ----------------
__device__ __align__(128) bf16 g_inp_h[(size_t)NBT*Hsz];
__device__ __align__(128) bf16 g_inp_l[(size_t)NBT*Hsz];
__device__ __align__(128) bf16 g_seq_h[(size_t)NBT*Hsz];
__device__ __align__(128) bf16 g_seq_l[(size_t)NBT*Hsz];
__device__ __align__(128) float g_xgT[(size_t)G4*NBT];     // [n][t*512+b]
__device__ __align__(128) bf16 g_h0h[Bsz*Hsz], g_h0l[Bsz*Hsz];
__device__ __align__(128) bf16 g_h1h[Bsz*Hsz], g_h1l[Bsz*Hsz];
__device__ __align__(128) float g_c[Bsz*Hsz];
__device__ __align__(128) bf16 g_Wih_h[2*(size_t)G4*Hsz], g_Wih_l[2*(size_t)G4*Hsz];
__device__ __align__(128) bf16 g_Whh_h[2*(size_t)G4*Hsz], g_Whh_l[2*(size_t)G4*Hsz];
__device__ __align__(128) bf16 g_dW_h[(size_t)Vsz*Hsz],   g_dW_l[(size_t)Vsz*Hsz];

// ---------------- helpers ----------------
__device__ __forceinline__ uint32_t smem_u32(const void* p){
    uint32_t a; asm("{ .reg .u64 t; cvta.to.shared.u64 t, %1; cvt.u32.u64 %0, t; }" : "=r"(a) : "l"(p)); return a;
}
#define CP16(dst, src) asm volatile("cp.async.cg.shared.global [%0], [%1], 16;" :: "r"(dst), "l"(src))
#define CPCOMMIT()     asm volatile("cp.async.commit_group;" ::: "memory")
#define CPWAIT(n)      asm volatile("cp.async.wait_group %0;" :: "n"(n) : "memory")

__device__ __forceinline__ void mma16816(float* d, const uint32_t* a, const uint32_t* b){
    asm volatile("mma.sync.aligned.m16n8k16.row.col.f32.bf16.bf16.f32 "
        "{%0,%1,%2,%3}, {%4,%5,%6,%7}, {%8,%9}, {%0,%1,%2,%3};"
        : "+f"(d[0]), "+f"(d[1]), "+f"(d[2]), "+f"(d[3])
        : "r"(a[0]), "r"(a[1]), "r"(a[2]), "r"(a[3]), "r"(b[0]), "r"(b[1]));
}

// SMEM geometry: per chunk (BK=32 bf16 = 16 words/row, padded to 20 words = 80B)
// per matrix: 128 rows * 20 words = 2560 words = 10240 B.
// stage = [Ah][Al][Bh][Bl] = 4*2560 = 10240 words = 40960 B; 2 stages = 81920 B.
#define CHW 2560
#define STW 10240
#define SMEMB 81920

// bmap: 0 = direct B row; 1 = layer-2 seq map (bt -> b*128+t); 2 = lstm gate map (n0=u0)
__device__ __forceinline__ void load_chunk(uint32_t sbase,
    const bf16* __restrict__ Ah, const bf16* __restrict__ Al,
    const bf16* __restrict__ Bh, const bf16* __restrict__ Bl,
    int m0, int n0, int ck, int bmap, int tid)
{
    #pragma unroll
    for (int i = tid; i < 512; i += 256) {
        int r = i >> 2, q = i & 3;
        uint32_t d = sbase + (r*20 + q*4)*4;
        size_t src = (size_t)(m0 + r)*Hsz + ck*32 + q*8;
        CP16(d,              Ah + src);
        CP16(d + CHW*4,      Al + src);
    }
    #pragma unroll
    for (int i = tid; i < 512; i += 256) {
        int r = i >> 2, q = i & 3;
        int brow;
        if (bmap == 0)      brow = n0 + r;
        else if (bmap == 1) { int c = n0 + r; brow = (c & 511)*Tsz + (c >> 9); }
        else                brow = ((r >> 3) & 3)*Hsz + n0 + (r >> 5)*8 + (r & 7);
        uint32_t d = sbase + (2*CHW + r*20 + q*4)*4;
        size_t src = (size_t)brow*Hsz + ck*32 + q*8;
        CP16(d,              Bh + src);
        CP16(d + CHW*4,      Bl + src);
    }
    CPCOMMIT();
}

__device__ __forceinline__ void compute_chunk(const uint32_t* __restrict__ sm,
    float acc[4][4][4], int lane, int wm, int wn)
{
    const uint32_t* sAh = sm;
    const uint32_t* sAl = sm + CHW;
    const uint32_t* sBh = sm + 2*CHW;
    const uint32_t* sBl = sm + 3*CHW;
    int laneR = lane >> 2, laneC = lane & 3;
    #pragma unroll
    for (int ks = 0; ks < 2; ks++) {
        int kw = ks*8 + laneC;
        uint32_t ah[4][4], al[4][4], bh[4][2], bl[4][2];
        #pragma unroll
        for (int mt = 0; mt < 4; mt++) {
            int r = wm*64 + mt*16 + laneR;
            ah[mt][0] = sAh[r*20+kw];       ah[mt][1] = sAh[(r+8)*20+kw];
            ah[mt][2] = sAh[r*20+kw+4];     ah[mt][3] = sAh[(r+8)*20+kw+4];
            al[mt][0] = sAl[r*20+kw];       al[mt][1] = sAl[(r+8)*20+kw];
            al[mt][2] = sAl[r*20+kw+4];     al[mt][3] = sAl[(r+8)*20+kw+4];
        }
        #pragma unroll
        for (int nt = 0; nt < 4; nt++) {
            int rr = wn*32 + nt*8 + laneR;
            bh[nt][0] = sBh[rr*20+kw];      bh[nt][1] = sBh[rr*20+kw+4];
            bl[nt][0] = sBl[rr*20+kw];      bl[nt][1] = sBl[rr*20+kw+4];
        }
        #pragma unroll
        for (int mt = 0; mt < 4; mt++)
        #pragma unroll
        for (int nt = 0; nt < 4; nt++) {
            mma16816(acc[mt][nt], ah[mt], bh[nt]);
            mma16816(acc[mt][nt], ah[mt], bl[nt]);
            mma16816(acc[mt][nt], al[mt], bh[nt]);
        }
    }
}

// ---------------- generic GEMM: C[m][n] = A[m][:]·B[brow(n)][:] + bias ----------------
__global__ void __launch_bounds__(256)
gemm_mma(const bf16* __restrict__ Ah, const bf16* __restrict__ Al,
         const bf16* __restrict__ Bh, const bf16* __restrict__ Bl,
         const float* __restrict__ br1, const float* __restrict__ br2,
         const float* __restrict__ bcn, float* __restrict__ C,
         int Ntot, int bmap, int mx)
{
    extern __shared__ uint32_t sm[];
    uint32_t sbase = smem_u32(sm);
    int tid = threadIdx.x, lane = tid & 31, wid = tid >> 5;
    int wm = wid >> 2, wn = wid & 3;
    int bm = mx ? blockIdx.x : blockIdx.y;
    int bn = mx ? blockIdx.y : blockIdx.x;
    int m0 = bm*128, n0 = bn*128;

    float acc[4][4][4];
    #pragma unroll
    for (int a = 0; a < 4; a++)
    #pragma unroll
    for (int b = 0; b < 4; b++)
    #pragma unroll
    for (int cc = 0; cc < 4; cc++) acc[a][b][cc] = 0.f;

    load_chunk(sbase, Ah, Al, Bh, Bl, m0, n0, 0, bmap, tid);
    for (int k = 0; k < 16; k++) {
        int st = k & 1;
        if (k < 15) {
            load_chunk(sbase + (st^1)*STW*4, Ah, Al, Bh, Bl, m0, n0, k+1, bmap, tid);
            CPWAIT(1);
        } else {
            CPWAIT(0);
        }
        __syncthreads();
        compute_chunk(sm + st*STW, acc, lane, wm, wn);
        __syncthreads();
    }

    #pragma unroll
    for (int mt = 0; mt < 4; mt++) {
        #pragma unroll
        for (int half = 0; half < 2; half++) {
            int m = m0 + wm*64 + mt*16 + (lane >> 2) + half*8;
            float rb = br1 ? (br1[m] + br2[m]) : 0.f;
            #pragma unroll
            for (int nt = 0; nt < 4; nt++) {
                int c = n0 + wn*32 + nt*8 + (lane & 3)*2;
                float v0 = acc[mt][nt][half*2+0] + rb;
                float v1 = acc[mt][nt][half*2+1] + rb;
                if (bcn) { v0 += bcn[c]; v1 += bcn[c+1]; }
                *(float2*)(C + (size_t)m*Ntot + c) = make_float2(v0, v1);
            }
        }
    }
}

// ---------------- fused LSTM step ----------------
// M = batch (grid.x*128), N-block = 32 units x 4 gates (grid.y*32 = u0).
__global__ void __launch_bounds__(256)
lstm_mma(const float* __restrict__ xgT,
         const bf16* __restrict__ Wh, const bf16* __restrict__ Wl,
         const bf16* __restrict__ hinh, const bf16* __restrict__ hinl,
         bf16* __restrict__ houth, bf16* __restrict__ houtl,
         float* __restrict__ cst, bf16* __restrict__ seqh, bf16* __restrict__ seql,
         int t)
{
    extern __shared__ uint32_t sm[];
    uint32_t sbase = smem_u32(sm);
    int tid = threadIdx.x, lane = tid & 31, wid = tid >> 5;
    int wm = wid >> 2, wn = wid & 3;
    int m0 = blockIdx.x*128;          // batch base
    int u0 = blockIdx.y*32;           // unit base

    float acc[4][4][4];
    #pragma unroll
    for (int a = 0; a < 4; a++)
    #pragma unroll
    for (int b = 0; b < 4; b++)
    #pragma unroll
    for (int cc = 0; cc < 4; cc++) acc[a][b][cc] = 0.f;

    load_chunk(sbase, hinh, hinl, Wh, Wl, m0, u0, 0, 2, tid);
    for (int k = 0; k < 16; k++) {
        int st = k & 1;
        if (k < 15) {
            load_chunk(sbase + (st^1)*STW*4, hinh, hinl, Wh, Wl, m0, u0, k+1, 2, tid);
            CPWAIT(1);
        } else {
            CPWAIT(0);
        }
        __syncthreads();
        compute_chunk(sm + st*STW, acc, lane, wm, wn);
        __syncthreads();
    }

    // epilogue: thread holds 8 batch rows x 2 units x 4 gates (gate = nt)
    int uu = u0 + wn*8 + (lane & 3)*2;      // units uu, uu+1
    #pragma unroll
    for (int mt = 0; mt < 4; mt++) {
        #pragma unroll
        for (int half = 0; half < 2; half++) {
            int b = m0 + wm*64 + mt*16 + (lane >> 2) + half*8;
            size_t xb = (size_t)t*Bsz + b;
            float cn[2], hn[2];
            #pragma unroll
            for (int j = 0; j < 2; j++) {
                int u = uu + j;
                int q = half*2 + j;
                float gi = acc[mt][0][q] + xgT[(size_t)(0*Hsz + u)*NBT + xb];
                float gf = acc[mt][1][q] + xgT[(size_t)(1*Hsz + u)*NBT + xb];
                float gg = acc[mt][2][q] + xgT[(size_t)(2*Hsz + u)*NBT + xb];
                float go = acc[mt][3][q] + xgT[(size_t)(3*Hsz + u)*NBT + xb];
                float is = 1.f/(1.f + __expf(-gi));
                float fs = 1.f/(1.f + __expf(-gf));
                float os = 1.f/(1.f + __expf(-go));
                float gt = tanhf(gg);
                float cold = cst[(size_t)b*Hsz + uu + j];
                cn[j] = fs*cold + is*gt;
                hn[j] = os * tanhf(cn[j]);
            }
            size_t so = (size_t)b*Hsz + uu;
            *(float2*)(cst + so) = make_float2(cn[0], cn[1]);
            bf16 h0 = __float2bfloat16_rn(hn[0]);
            bf16 h1 = __float2bfloat16_rn(hn[1]);
            bf16 l0 = __float2bfloat16_rn(hn[0] - __bfloat162float(h0));
            bf16 l1 = __float2bfloat16_rn(hn[1] - __bfloat162float(h1));
            __nv_bfloat162 hp; hp.x = h0; hp.y = h1;
            __nv_bfloat162 lp; lp.x = l0; lp.y = l1;
            *(__nv_bfloat162*)(houth + so) = hp;
            *(__nv_bfloat162*)(houtl + so) = lp;
            size_t qo = ((size_t)b*Tsz + t)*Hsz + uu;
            *(__nv_bfloat162*)(seqh + qo) = hp;
            *(__nv_bfloat162*)(seql + qo) = lp;
        }
    }
}

// ---------------- small kernels ----------------
__global__ void split_kernel(const float* __restrict__ s, bf16* __restrict__ h,
                             bf16* __restrict__ l, int n){
    int i = blockIdx.x*blockDim.x + threadIdx.x;
    if (i < n) {
        float v = s[i];
        bf16 hv = __float2bfloat16_rn(v);
        h[i] = hv;
        l[i] = __float2bfloat16_rn(v - __bfloat162float(hv));
    }
}
__global__ void embed_kernel(const int* __restrict__ x, const float* __restrict__ y,
                             const float* __restrict__ emb, const float* __restrict__ yW,
                             const float* __restrict__ yb, bf16* __restrict__ oh, bf16* __restrict__ ol){
    int bt = blockIdx.x;            // bt = t*512 + b (t-major)
    int t = bt >> 9, b = bt & 511;
    int h = threadIdx.x;
    int tok = (t == 0) ? Vsz : x[b*Tsz + t - 1];
    float v = emb[(size_t)tok*Hsz + h] + y[b]*yW[h] + yb[h];
    bf16 hv = __float2bfloat16_rn(v);
    oh[(size_t)bt*Hsz + h] = hv;
    ol[(size_t)bt*Hsz + h] = __float2bfloat16_rn(v - __bfloat162float(hv));
}
__global__ void zero_kernel(bf16* hb, bf16* lb, float* c){
    int i = blockIdx.x*blockDim.x + threadIdx.x;
    if (i < Bsz*Hsz) { c[i] = 0.f; hb[i] = __float2bfloat16(0.f); lb[i] = __float2bfloat16(0.f); }
}

// ---------------- launch ----------------
extern "C" void kernel_launch(void* const* d_in, const int* in_sizes, int n_in,
                              void* d_out, int out_size)
{
    const int*   x    = (const int*)  d_in[0];
    const float* y    = (const float*)d_in[1];
    const float* emb  = (const float*)d_in[2];
    const float* yW   = (const float*)d_in[3];
    const float* yb   = (const float*)d_in[4];
    const float* Wih  = (const float*)d_in[5];
    const float* Whh  = (const float*)d_in[6];
    const float* bih  = (const float*)d_in[7];
    const float* bhh  = (const float*)d_in[8];
    const float* decW = (const float*)d_in[9];
    const float* decb = (const float*)d_in[10];
    float* out = (float*)d_out;

    bf16 *inp_h, *inp_l, *seq_h, *seq_l, *Wih_h, *Wih_l, *Whh_h, *Whh_l, *dW_h, *dW_l;
    bf16 *h0h, *h0l, *h1h, *h1l;
    float *xgT, *c;
    cudaGetSymbolAddress((void**)&inp_h, g_inp_h);
    cudaGetSymbolAddress((void**)&inp_l, g_inp_l);
    cudaGetSymbolAddress((void**)&seq_h, g_seq_h);
    cudaGetSymbolAddress((void**)&seq_l, g_seq_l);
    cudaGetSymbolAddress((void**)&xgT,   g_xgT);
    cudaGetSymbolAddress((void**)&h0h,   g_h0h);
    cudaGetSymbolAddress((void**)&h0l,   g_h0l);
    cudaGetSymbolAddress((void**)&h1h,   g_h1h);
    cudaGetSymbolAddress((void**)&h1l,   g_h1l);
    cudaGetSymbolAddress((void**)&c,     g_c);
    cudaGetSymbolAddress((void**)&Wih_h, g_Wih_h);
    cudaGetSymbolAddress((void**)&Wih_l, g_Wih_l);
    cudaGetSymbolAddress((void**)&Whh_h, g_Whh_h);
    cudaGetSymbolAddress((void**)&Whh_l, g_Whh_l);
    cudaGetSymbolAddress((void**)&dW_h,  g_dW_h);
    cudaGetSymbolAddress((void**)&dW_l,  g_dW_l);
    bf16* hph[2] = { h0h, h1h };
    bf16* hpl[2] = { h0l, h1l };

    cudaFuncSetAttribute(gemm_mma, cudaFuncAttributeMaxDynamicSharedMemorySize, SMEMB);
    cudaFuncSetAttribute(lstm_mma, cudaFuncAttributeMaxDynamicSharedMemorySize, SMEMB);

    const int nW = 2*G4*Hsz;
    split_kernel<<<(nW+255)/256, 256>>>(Wih, Wih_h, Wih_l, nW);
    split_kernel<<<(nW+255)/256, 256>>>(Whh, Whh_h, Whh_l, nW);
    split_kernel<<<(Vsz*Hsz+255)/256, 256>>>(decW, dW_h, dW_l, Vsz*Hsz);
    embed_kernel<<<NBT, Hsz>>>(x, y, emb, yW, yb, inp_h, inp_l);

    for (int l = 0; l < 2; l++) {
        const bf16* Bh = l ? seq_h : inp_h;
        const bf16* Bl = l ? seq_l : inp_l;
        // xgT[n][bt] = Wih[n]·inp[bt] + bih[n] + bhh[n]; grid x=M(gates),y=N(bt)
        gemm_mma<<<dim3(G4/128, NBT/128), 256, SMEMB>>>(
            Wih_h + (size_t)l*G4*Hsz, Wih_l + (size_t)l*G4*Hsz,
            Bh, Bl, bih + l*G4, bhh + l*G4, nullptr, xgT, NBT, l ? 1 : 0, 1);

        zero_kernel<<<(Bsz*Hsz+255)/256, 256>>>(hph[0], hpl[0], c);

        for (int t = 0; t < Tsz; t++) {
            lstm_mma<<<dim3(Bsz/128, Hsz/32), 256, SMEMB>>>(
                xgT, Whh_h + (size_t)l*G4*Hsz, Whh_l + (size_t)l*G4*Hsz,
                hph[t & 1], hpl[t & 1], hph[(t+1) & 1], hpl[(t+1) & 1],
                c, seq_h, seq_l, t);
        }
    }

    // decoder: out[b*T+t][v] = seq·decW^T + decb; A=seq rows (m=b*128+t), N=512
    // grid: x = N blocks (4), y = M blocks (512) -> mx=0
    gemm_mma<<<dim3(Vsz/128, NBT/128), 256, SMEMB>>>(
        seq_h, seq_l, dW_h, dW_l, nullptr, nullptr, decb, out, Vsz, 0, 0);
}

// round 5
// speedup vs baseline: 2.6808x; 1.4660x over previous
#include <cuda_runtime.h>
#include <cuda_bf16.h>
#include <stdint.h>
#include <math.h>

#define Bsz 512
#define Tsz 128
#define Hsz 512
#define Vsz 512
#define NBT 65536
#define G4  2048
typedef __nv_bfloat16 bf16;

// ---------------- device scratch ----------------
__device__ __align__(128) bf16 g_inp_h[(size_t)NBT*Hsz];
__device__ __align__(128) bf16 g_inp_l[(size_t)NBT*Hsz];
__device__ __align__(128) bf16 g_seq_h[(size_t)NBT*Hsz];
__device__ __align__(128) bf16 g_seq_l[(size_t)NBT*Hsz];
__device__ __align__(128) float g_xgT[(size_t)Tsz*G4*Bsz];   // [t][n][b]
__device__ __align__(128) bf16 g_h0h[Bsz*Hsz], g_h0l[Bsz*Hsz];
__device__ __align__(128) bf16 g_h1h[Bsz*Hsz], g_h1l[Bsz*Hsz];
__device__ __align__(128) float g_c[Bsz*Hsz];
__device__ __align__(128) bf16 g_Wih_h[2*(size_t)G4*Hsz], g_Wih_l[2*(size_t)G4*Hsz];
__device__ __align__(128) bf16 g_Whh_h[2*(size_t)G4*Hsz], g_Whh_l[2*(size_t)G4*Hsz];
__device__ __align__(128) bf16 g_dW_h[(size_t)Vsz*Hsz],   g_dW_l[(size_t)Vsz*Hsz];
__device__ unsigned g_gen, g_cnt;

// ---------------- helpers ----------------
__device__ __forceinline__ uint32_t smem_u32(const void* p){
    uint32_t a; asm("{ .reg .u64 t; cvta.to.shared.u64 t, %1; cvt.u32.u64 %0, t; }" : "=r"(a) : "l"(p)); return a;
}
#define CP16(dst, src) asm volatile("cp.async.cg.shared.global [%0], [%1], 16;" :: "r"(dst), "l"(src))
#define CPCOMMIT()     asm volatile("cp.async.commit_group;" ::: "memory")
#define CPWAIT(n)      asm volatile("cp.async.wait_group %0;" :: "n"(n) : "memory")

__device__ __forceinline__ void mma16816(float* d, const uint32_t* a, const uint32_t* b){
    asm volatile("mma.sync.aligned.m16n8k16.row.col.f32.bf16.bf16.f32 "
        "{%0,%1,%2,%3}, {%4,%5,%6,%7}, {%8,%9}, {%0,%1,%2,%3};"
        : "+f"(d[0]), "+f"(d[1]), "+f"(d[2]), "+f"(d[3])
        : "r"(a[0]), "r"(a[1]), "r"(a[2]), "r"(a[3]), "r"(b[0]), "r"(b[1]));
}

// ============ generic FF GEMM (from R4, + cmode for xg layout) ============
#define CHW 2560
#define STW 10240
#define SMEMB 81920

__device__ __forceinline__ void load_chunk(uint32_t sbase,
    const bf16* __restrict__ Ah, const bf16* __restrict__ Al,
    const bf16* __restrict__ Bh, const bf16* __restrict__ Bl,
    int m0, int n0, int ck, int bmap, int tid)
{
    #pragma unroll
    for (int i = tid; i < 512; i += 256) {
        int r = i >> 2, q = i & 3;
        uint32_t d = sbase + (r*20 + q*4)*4;
        size_t src = (size_t)(m0 + r)*Hsz + ck*32 + q*8;
        CP16(d,         Ah + src);
        CP16(d + CHW*4, Al + src);
    }
    #pragma unroll
    for (int i = tid; i < 512; i += 256) {
        int r = i >> 2, q = i & 3;
        int brow;
        if (bmap == 0)      brow = n0 + r;
        else                { int c = n0 + r; brow = (c & 511)*Tsz + (c >> 9); }
        uint32_t d = sbase + (2*CHW + r*20 + q*4)*4;
        size_t src = (size_t)brow*Hsz + ck*32 + q*8;
        CP16(d,         Bh + src);
        CP16(d + CHW*4, Bl + src);
    }
    CPCOMMIT();
}

__device__ __forceinline__ void compute_chunk(const uint32_t* __restrict__ sm,
    float acc[4][4][4], int lane, int wm, int wn)
{
    const uint32_t* sAh = sm;
    const uint32_t* sAl = sm + CHW;
    const uint32_t* sBh = sm + 2*CHW;
    const uint32_t* sBl = sm + 3*CHW;
    int laneR = lane >> 2, laneC = lane & 3;
    #pragma unroll
    for (int ks = 0; ks < 2; ks++) {
        int kw = ks*8 + laneC;
        uint32_t ah[4][4], al[4][4], bh[4][2], bl[4][2];
        #pragma unroll
        for (int mt = 0; mt < 4; mt++) {
            int r = wm*64 + mt*16 + laneR;
            ah[mt][0] = sAh[r*20+kw];       ah[mt][1] = sAh[(r+8)*20+kw];
            ah[mt][2] = sAh[r*20+kw+4];     ah[mt][3] = sAh[(r+8)*20+kw+4];
            al[mt][0] = sAl[r*20+kw];       al[mt][1] = sAl[(r+8)*20+kw];
            al[mt][2] = sAl[r*20+kw+4];     al[mt][3] = sAl[(r+8)*20+kw+4];
        }
        #pragma unroll
        for (int nt = 0; nt < 4; nt++) {
            int rr = wn*32 + nt*8 + laneR;
            bh[nt][0] = sBh[rr*20+kw];      bh[nt][1] = sBh[rr*20+kw+4];
            bl[nt][0] = sBl[rr*20+kw];      bl[nt][1] = sBl[rr*20+kw+4];
        }
        #pragma unroll
        for (int mt = 0; mt < 4; mt++)
        #pragma unroll
        for (int nt = 0; nt < 4; nt++) {
            mma16816(acc[mt][nt], ah[mt], bh[nt]);
            mma16816(acc[mt][nt], ah[mt], bl[nt]);
            mma16816(acc[mt][nt], al[mt], bh[nt]);
        }
    }
}

__global__ void __launch_bounds__(256)
gemm_mma(const bf16* __restrict__ Ah, const bf16* __restrict__ Al,
         const bf16* __restrict__ Bh, const bf16* __restrict__ Bl,
         const float* __restrict__ br1, const float* __restrict__ br2,
         const float* __restrict__ bcn, float* __restrict__ C,
         int Ntot, int bmap, int mx, int cmode)
{
    extern __shared__ uint32_t sm[];
    uint32_t sbase = smem_u32(sm);
    int tid = threadIdx.x, lane = tid & 31, wid = tid >> 5;
    int wm = wid >> 2, wn = wid & 3;
    int bm = mx ? blockIdx.x : blockIdx.y;
    int bn = mx ? blockIdx.y : blockIdx.x;
    int m0 = bm*128, n0 = bn*128;

    float acc[4][4][4];
    #pragma unroll
    for (int a = 0; a < 4; a++)
    #pragma unroll
    for (int b = 0; b < 4; b++)
    #pragma unroll
    for (int cc = 0; cc < 4; cc++) acc[a][b][cc] = 0.f;

    load_chunk(sbase, Ah, Al, Bh, Bl, m0, n0, 0, bmap, tid);
    for (int k = 0; k < 16; k++) {
        int st = k & 1;
        if (k < 15) {
            load_chunk(sbase + (st^1)*STW*4, Ah, Al, Bh, Bl, m0, n0, k+1, bmap, tid);
            CPWAIT(1);
        } else {
            CPWAIT(0);
        }
        __syncthreads();
        compute_chunk(sm + st*STW, acc, lane, wm, wn);
        __syncthreads();
    }

    #pragma unroll
    for (int mt = 0; mt < 4; mt++) {
        #pragma unroll
        for (int half = 0; half < 2; half++) {
            int m = m0 + wm*64 + mt*16 + (lane >> 2) + half*8;
            float rb = br1 ? (br1[m] + br2[m]) : 0.f;
            #pragma unroll
            for (int nt = 0; nt < 4; nt++) {
                int c = n0 + wn*32 + nt*8 + (lane & 3)*2;
                float v0 = acc[mt][nt][half*2+0] + rb;
                float v1 = acc[mt][nt][half*2+1] + rb;
                if (bcn) { v0 += bcn[c]; v1 += bcn[c+1]; }
                if (cmode) {
                    float* dst = C + ((size_t)(c >> 9)*G4 + m)*Bsz + (c & 511);
                    *(float2*)dst = make_float2(v0, v1);
                } else {
                    *(float2*)(C + (size_t)m*Ntot + c) = make_float2(v0, v1);
                }
            }
        }
    }
}

// ============ persistent LSTM recurrence ============
// grid (32,4): blockIdx.x -> 16 units (u0), blockIdx.y -> 128 batch (b0).
// SMEM: W[hi/lo][16ck][64r][20w] = 163840B, H[2st][hi/lo][128r][20w] = 40960B
#define PS_SMEM 204800
__device__ __forceinline__ int WOFFf(int hl,int ck,int r){ return (((hl)*16+(ck))*64 + (r))*20; }
__device__ __forceinline__ int HOFFf(int st,int hl,int r){ return 40960 + ((((st)*2+(hl))*128) + (r))*20; }

__global__ void reset_bar(){ g_gen = 0; g_cnt = 0; }

__global__ void __launch_bounds__(256,1)
lstm_persist(const float* __restrict__ xg,
             const bf16* __restrict__ Wh, const bf16* __restrict__ Wl,
             bf16* __restrict__ h0h, bf16* __restrict__ h0l,
             bf16* __restrict__ h1h, bf16* __restrict__ h1l,
             float* __restrict__ cst, bf16* __restrict__ seqh, bf16* __restrict__ seql)
{
    extern __shared__ uint32_t sm[];
    uint32_t sb = smem_u32(sm);
    int tid = threadIdx.x, lane = tid & 31, w = tid >> 5;
    int laneR = lane >> 2, laneC = lane & 3;
    int u0 = blockIdx.x * 16;
    int b0 = blockIdx.y * 128;
    unsigned nCTA = gridDim.x * gridDim.y;

    // ---- persistent W tile: rows n = g*16+ul -> Whh row g*512 + u0+ul ----
    for (int i = tid; i < 8192; i += 256) {
        int hl = i >> 12, j = i & 4095;
        int r = j >> 6, q = j & 63;
        int ck = q >> 2, wq = q & 3;
        int g = r >> 4, ul = r & 15;
        const bf16* src = (hl ? Wl : Wh) + ((size_t)(g*Hsz + u0 + ul))*Hsz + q*8;
        CP16(sb + (WOFFf(hl,ck,r) + wq*4)*4, src);
    }
    CPCOMMIT(); CPWAIT(0);
    __syncthreads();

    bf16* hh[2] = {h0h, h1h};
    bf16* hl2[2] = {h0l, h1l};

    for (int t = 0; t < Tsz; t++) {
        const bf16* Hh = hh[t & 1];
        const bf16* Hl = hl2[t & 1];
        bf16* Nh = hh[(t+1) & 1];
        bf16* Nl = hl2[(t+1) & 1];

        // prefetch this thread's xg values (independent of h)
        float xv[2][16];
        {
            const float* xgt = xg + (size_t)t*G4*Bsz;
            #pragma unroll
            for (int half = 0; half < 2; half++) {
                int b = b0 + w*16 + laneR + half*8;
                #pragma unroll
                for (int uh = 0; uh < 2; uh++)
                #pragma unroll
                for (int du = 0; du < 2; du++) {
                    int u = u0 + laneC*2 + uh*8 + du;
                    #pragma unroll
                    for (int g = 0; g < 4; g++)
                        xv[half][uh*8 + du*4 + g] = xgt[((size_t)(g*Hsz + u))*Bsz + b];
                }
            }
        }

        float acc[8][4];
        #pragma unroll
        for (int i = 0; i < 8; i++)
        #pragma unroll
        for (int j = 0; j < 4; j++) acc[i][j] = 0.f;

        // h chunk loader
        auto ldh = [&](int ck, int st){
            #pragma unroll
            for (int i = tid; i < 512; i += 256) {
                int r = i >> 2, q = i & 3;
                size_t src = (size_t)(b0 + r)*Hsz + ck*32 + q*8;
                CP16(sb + (HOFFf(st,0,r) + q*4)*4, Hh + src);
                CP16(sb + (HOFFf(st,1,r) + q*4)*4, Hl + src);
            }
            CPCOMMIT();
        };

        ldh(0, 0);
        for (int ck = 0; ck < 16; ck++) {
            int st = ck & 1;
            if (ck < 15) { ldh(ck+1, st^1); CPWAIT(1); } else { CPWAIT(0); }
            __syncthreads();
            #pragma unroll
            for (int ks = 0; ks < 2; ks++) {
                int kw = ks*8 + laneC;
                uint32_t ah[4], al[4];
                int r = w*16 + laneR;
                ah[0] = sm[HOFFf(st,0,r)   + kw];
                ah[1] = sm[HOFFf(st,0,r+8) + kw];
                ah[2] = sm[HOFFf(st,0,r)   + kw + 4];
                ah[3] = sm[HOFFf(st,0,r+8) + kw + 4];
                al[0] = sm[HOFFf(st,1,r)   + kw];
                al[1] = sm[HOFFf(st,1,r+8) + kw];
                al[2] = sm[HOFFf(st,1,r)   + kw + 4];
                al[3] = sm[HOFFf(st,1,r+8) + kw + 4];
                #pragma unroll
                for (int nt = 0; nt < 8; nt++) {
                    int rr = nt*8 + laneR;
                    uint32_t bh[2], bl[2];
                    bh[0] = sm[WOFFf(0,ck,rr) + kw];
                    bh[1] = sm[WOFFf(0,ck,rr) + kw + 4];
                    bl[0] = sm[WOFFf(1,ck,rr) + kw];
                    bl[1] = sm[WOFFf(1,ck,rr) + kw + 4];
                    mma16816(acc[nt], ah, bh);
                    mma16816(acc[nt], ah, bl);
                    mma16816(acc[nt], al, bh);
                }
            }
            __syncthreads();
        }

        // epilogue: gates + state update; thread owns all 4 gates of its units
        #pragma unroll
        for (int half = 0; half < 2; half++) {
            int b = b0 + w*16 + laneR + half*8;
            #pragma unroll
            for (int uh = 0; uh < 2; uh++) {
                float cn[2], hn[2];
                #pragma unroll
                for (int du = 0; du < 2; du++) {
                    int q = half*2 + du;
                    float gi = acc[0*2+uh][q] + xv[half][uh*8+du*4+0];
                    float gf = acc[1*2+uh][q] + xv[half][uh*8+du*4+1];
                    float gg = acc[2*2+uh][q] + xv[half][uh*8+du*4+2];
                    float go = acc[3*2+uh][q] + xv[half][uh*8+du*4+3];
                    float is = 1.f/(1.f + __expf(-gi));
                    float fs = 1.f/(1.f + __expf(-gf));
                    float os = 1.f/(1.f + __expf(-go));
                    float gt = tanhf(gg);
                    int u = u0 + laneC*2 + uh*8 + du;
                    float co = cst[(size_t)b*Hsz + u];
                    cn[du] = fs*co + is*gt;
                    hn[du] = os*tanhf(cn[du]);
                }
                int u2 = u0 + laneC*2 + uh*8;
                size_t so = (size_t)b*Hsz + u2;
                *(float2*)(cst + so) = make_float2(cn[0], cn[1]);
                bf16 hb0 = __float2bfloat16_rn(hn[0]);
                bf16 hb1 = __float2bfloat16_rn(hn[1]);
                __nv_bfloat162 hp; hp.x = hb0; hp.y = hb1;
                __nv_bfloat162 lp;
                lp.x = __float2bfloat16_rn(hn[0] - __bfloat162float(hb0));
                lp.y = __float2bfloat16_rn(hn[1] - __bfloat162float(hb1));
                *(__nv_bfloat162*)(Nh + so) = hp;
                *(__nv_bfloat162*)(Nl + so) = lp;
                size_t qo = ((size_t)b*Tsz + t)*Hsz + u2;
                *(__nv_bfloat162*)(seqh + qo) = hp;
                *(__nv_bfloat162*)(seql + qo) = lp;
            }
        }

        // ---- grid barrier (not after final step) ----
        if (t < Tsz - 1) {
            __threadfence();
            __syncthreads();
            if (tid == 0) {
                unsigned target = (unsigned)(t + 1);
                if (atomicAdd(&g_cnt, 1u) == nCTA - 1u) {
                    atomicExch(&g_cnt, 0u);
                    __threadfence();
                    atomicAdd(&g_gen, 1u);
                } else {
                    unsigned v;
                    do { asm volatile("ld.acquire.gpu.global.u32 %0, [%1];" : "=r"(v) : "l"(&g_gen)); }
                    while (v < target);
                }
            }
            __syncthreads();
            __threadfence();
        }
    }
}

// ---------------- small kernels ----------------
__global__ void split_kernel(const float* __restrict__ s, bf16* __restrict__ h,
                             bf16* __restrict__ l, int n){
    int i = blockIdx.x*blockDim.x + threadIdx.x;
    if (i < n) {
        float v = s[i];
        bf16 hv = __float2bfloat16_rn(v);
        h[i] = hv;
        l[i] = __float2bfloat16_rn(v - __bfloat162float(hv));
    }
}
__global__ void embed_kernel(const int* __restrict__ x, const float* __restrict__ y,
                             const float* __restrict__ emb, const float* __restrict__ yW,
                             const float* __restrict__ yb, bf16* __restrict__ oh, bf16* __restrict__ ol){
    int bt = blockIdx.x;            // bt = t*512 + b
    int t = bt >> 9, b = bt & 511;
    int h = threadIdx.x;
    int tok = (t == 0) ? Vsz : x[b*Tsz + t - 1];
    float v = emb[(size_t)tok*Hsz + h] + y[b]*yW[h] + yb[h];
    bf16 hv = __float2bfloat16_rn(v);
    oh[(size_t)bt*Hsz + h] = hv;
    ol[(size_t)bt*Hsz + h] = __float2bfloat16_rn(v - __bfloat162float(hv));
}
__global__ void zero_kernel(bf16* hb, bf16* lb, float* c){
    int i = blockIdx.x*blockDim.x + threadIdx.x;
    if (i < Bsz*Hsz) { c[i] = 0.f; hb[i] = __float2bfloat16(0.f); lb[i] = __float2bfloat16(0.f); }
}

// ---------------- launch ----------------
extern "C" void kernel_launch(void* const* d_in, const int* in_sizes, int n_in,
                              void* d_out, int out_size)
{
    const int*   x    = (const int*)  d_in[0];
    const float* y    = (const float*)d_in[1];
    const float* emb  = (const float*)d_in[2];
    const float* yW   = (const float*)d_in[3];
    const float* yb   = (const float*)d_in[4];
    const float* Wih  = (const float*)d_in[5];
    const float* Whh  = (const float*)d_in[6];
    const float* bih  = (const float*)d_in[7];
    const float* bhh  = (const float*)d_in[8];
    const float* decW = (const float*)d_in[9];
    const float* decb = (const float*)d_in[10];
    float* out = (float*)d_out;

    bf16 *inp_h, *inp_l, *seq_h, *seq_l, *Wih_h, *Wih_l, *Whh_h, *Whh_l, *dW_h, *dW_l;
    bf16 *h0h, *h0l, *h1h, *h1l;
    float *xgT, *c;
    cudaGetSymbolAddress((void**)&inp_h, g_inp_h);
    cudaGetSymbolAddress((void**)&inp_l, g_inp_l);
    cudaGetSymbolAddress((void**)&seq_h, g_seq_h);
    cudaGetSymbolAddress((void**)&seq_l, g_seq_l);
    cudaGetSymbolAddress((void**)&xgT,   g_xgT);
    cudaGetSymbolAddress((void**)&h0h,   g_h0h);
    cudaGetSymbolAddress((void**)&h0l,   g_h0l);
    cudaGetSymbolAddress((void**)&h1h,   g_h1h);
    cudaGetSymbolAddress((void**)&h1l,   g_h1l);
    cudaGetSymbolAddress((void**)&c,     g_c);
    cudaGetSymbolAddress((void**)&Wih_h, g_Wih_h);
    cudaGetSymbolAddress((void**)&Wih_l, g_Wih_l);
    cudaGetSymbolAddress((void**)&Whh_h, g_Whh_h);
    cudaGetSymbolAddress((void**)&Whh_l, g_Whh_l);
    cudaGetSymbolAddress((void**)&dW_h,  g_dW_h);
    cudaGetSymbolAddress((void**)&dW_l,  g_dW_l);

    cudaFuncSetAttribute(gemm_mma, cudaFuncAttributeMaxDynamicSharedMemorySize, SMEMB);
    cudaFuncSetAttribute(lstm_persist, cudaFuncAttributeMaxDynamicSharedMemorySize, PS_SMEM);

    const int nW = 2*G4*Hsz;
    split_kernel<<<(nW+255)/256, 256>>>(Wih, Wih_h, Wih_l, nW);
    split_kernel<<<(nW+255)/256, 256>>>(Whh, Whh_h, Whh_l, nW);
    split_kernel<<<(Vsz*Hsz+255)/256, 256>>>(decW, dW_h, dW_l, Vsz*Hsz);
    embed_kernel<<<NBT, Hsz>>>(x, y, emb, yW, yb, inp_h, inp_l);

    for (int l = 0; l < 2; l++) {
        const bf16* Bh = l ? seq_h : inp_h;
        const bf16* Bl = l ? seq_l : inp_l;
        // xgT[t][n][b] = Wih[n]·inp[t,b] + bih[n] + bhh[n]
        gemm_mma<<<dim3(G4/128, NBT/128), 256, SMEMB>>>(
            Wih_h + (size_t)l*G4*Hsz, Wih_l + (size_t)l*G4*Hsz,
            Bh, Bl, bih + l*G4, bhh + l*G4, nullptr, xgT, NBT, l ? 1 : 0, 1, 1);

        zero_kernel<<<(Bsz*Hsz+255)/256, 256>>>(h0h, h0l, c);
        reset_bar<<<1, 1>>>();

        lstm_persist<<<dim3(Hsz/16, Bsz/128), 256, PS_SMEM>>>(
            xgT, Whh_h + (size_t)l*G4*Hsz, Whh_l + (size_t)l*G4*Hsz,
            h0h, h0l, h1h, h1l, c, seq_h, seq_l);
    }

    // decoder: out[(b*T+t)][v] = seq·decW^T + decb
    gemm_mma<<<dim3(Vsz/128, NBT/128), 256, SMEMB>>>(
        seq_h, seq_l, dW_h, dW_l, nullptr, nullptr, decb, out, Vsz, 0, 0, 0);
}

// round 6
// speedup vs baseline: 2.8270x; 1.0545x over previous
#include <cuda_runtime.h>
#include <cuda_bf16.h>
#include <stdint.h>
#include <math.h>

#define Bsz 512
#define Tsz 128
#define Hsz 512
#define Vsz 512
#define NBT 65536
#define G4  2048
typedef __nv_bfloat16 bf16;

// ---------------- device scratch ----------------
__device__ __align__(128) bf16 g_inp_h[(size_t)NBT*Hsz];
__device__ __align__(128) bf16 g_inp_l[(size_t)NBT*Hsz];
__device__ __align__(128) bf16 g_seq_h[(size_t)NBT*Hsz];
__device__ __align__(128) bf16 g_seq_l[(size_t)NBT*Hsz];
__device__ __align__(128) float g_xgT[(size_t)Tsz*G4*Bsz];   // [t][n][b]
__device__ __align__(128) bf16 g_h0h[Bsz*Hsz], g_h0l[Bsz*Hsz];
__device__ __align__(128) bf16 g_h1h[Bsz*Hsz], g_h1l[Bsz*Hsz];
__device__ __align__(128) float g_c[Bsz*Hsz];
__device__ __align__(128) bf16 g_Wih_h[2*(size_t)G4*Hsz], g_Wih_l[2*(size_t)G4*Hsz];
__device__ __align__(128) bf16 g_Whh_h[2*(size_t)G4*Hsz], g_Whh_l[2*(size_t)G4*Hsz];
__device__ __align__(128) bf16 g_dW_h[(size_t)Vsz*Hsz],   g_dW_l[(size_t)Vsz*Hsz];
__device__ unsigned g_gen[4], g_cnt[4];

// ---------------- helpers ----------------
__device__ __forceinline__ uint32_t smem_u32(const void* p){
    uint32_t a; asm("{ .reg .u64 t; cvta.to.shared.u64 t, %1; cvt.u32.u64 %0, t; }" : "=r"(a) : "l"(p)); return a;
}
#define CP16(dst, src) asm volatile("cp.async.cg.shared.global [%0], [%1], 16;" :: "r"(dst), "l"(src))
#define CPCOMMIT()     asm volatile("cp.async.commit_group;" ::: "memory")
#define CPWAIT(n)      asm volatile("cp.async.wait_group %0;" :: "n"(n) : "memory")
#define LDSM4(r, a) asm volatile("ldmatrix.sync.aligned.m8n8.x4.shared.b16 {%0,%1,%2,%3}, [%4];" \
    : "=r"((r)[0]),"=r"((r)[1]),"=r"((r)[2]),"=r"((r)[3]) : "r"(a))

__device__ __forceinline__ void mma16816(float* d, const uint32_t* a, const uint32_t* b){
    asm volatile("mma.sync.aligned.m16n8k16.row.col.f32.bf16.bf16.f32 "
        "{%0,%1,%2,%3}, {%4,%5,%6,%7}, {%8,%9}, {%0,%1,%2,%3};"
        : "+f"(d[0]), "+f"(d[1]), "+f"(d[2]), "+f"(d[3])
        : "r"(a[0]), "r"(a[1]), "r"(a[2]), "r"(a[3]), "r"(b[0]), "r"(b[1]));
}

// ============ generic FF GEMM ============
#define CHW 2560
#define STW 10240
#define SMEMB 81920

__device__ __forceinline__ void load_chunk(uint32_t sbase,
    const bf16* __restrict__ Ah, const bf16* __restrict__ Al,
    const bf16* __restrict__ Bh, const bf16* __restrict__ Bl,
    int m0, int n0, int ck, int bmap, int tid)
{
    #pragma unroll
    for (int i = tid; i < 512; i += 256) {
        int r = i >> 2, q = i & 3;
        uint32_t d = sbase + (r*20 + q*4)*4;
        size_t src = (size_t)(m0 + r)*Hsz + ck*32 + q*8;
        CP16(d,         Ah + src);
        CP16(d + CHW*4, Al + src);
    }
    #pragma unroll
    for (int i = tid; i < 512; i += 256) {
        int r = i >> 2, q = i & 3;
        int brow;
        if (bmap == 0)      brow = n0 + r;
        else                { int c = n0 + r; brow = (c & 511)*Tsz + (c >> 9); }
        uint32_t d = sbase + (2*CHW + r*20 + q*4)*4;
        size_t src = (size_t)brow*Hsz + ck*32 + q*8;
        CP16(d,         Bh + src);
        CP16(d + CHW*4, Bl + src);
    }
    CPCOMMIT();
}

__device__ __forceinline__ void compute_chunk(uint32_t stg,
    float acc[4][4][4], int lane, int wm, int wn)
{
    int laneA_r = lane & 15;
    int laneA_c = (lane >> 4) * 4;
    int laneB_r = (lane & 7) + ((lane >> 4) << 3);
    int laneB_c = ((lane >> 3) & 1) * 4;
    #pragma unroll
    for (int ks = 0; ks < 2; ks++) {
        int kw = ks*8;
        uint32_t ah[4][4], al[4][4], bh[2][4], bl[2][4];
        #pragma unroll
        for (int mt = 0; mt < 4; mt++) {
            uint32_t aw = (uint32_t)(wm*64 + mt*16 + laneA_r)*20 + kw + laneA_c;
            LDSM4(ah[mt], stg + aw*4);
            LDSM4(al[mt], stg + (CHW + aw)*4);
        }
        #pragma unroll
        for (int np = 0; np < 2; np++) {
            uint32_t bw = (uint32_t)(wn*32 + np*16 + laneB_r)*20 + kw + laneB_c;
            LDSM4(bh[np], stg + (2*CHW + bw)*4);
            LDSM4(bl[np], stg + (3*CHW + bw)*4);
        }
        #pragma unroll
        for (int mt = 0; mt < 4; mt++)
        #pragma unroll
        for (int nt = 0; nt < 4; nt++) {
            const uint32_t* BH = &bh[nt>>1][(nt&1)*2];
            const uint32_t* BL = &bl[nt>>1][(nt&1)*2];
            mma16816(acc[mt][nt], ah[mt], BH);
            mma16816(acc[mt][nt], ah[mt], BL);
            mma16816(acc[mt][nt], al[mt], BH);
        }
    }
}

__global__ void __launch_bounds__(256)
gemm_mma(const bf16* __restrict__ Ah, const bf16* __restrict__ Al,
         const bf16* __restrict__ Bh, const bf16* __restrict__ Bl,
         const float* __restrict__ br1, const float* __restrict__ br2,
         const float* __restrict__ bcn, float* __restrict__ C,
         int Ntot, int bmap, int mx, int cmode)
{
    extern __shared__ uint32_t sm[];
    uint32_t sbase = smem_u32(sm);
    int tid = threadIdx.x, lane = tid & 31, wid = tid >> 5;
    int wm = wid >> 2, wn = wid & 3;
    int bm = mx ? blockIdx.x : blockIdx.y;
    int bn = mx ? blockIdx.y : blockIdx.x;
    int m0 = bm*128, n0 = bn*128;

    float acc[4][4][4];
    #pragma unroll
    for (int a = 0; a < 4; a++)
    #pragma unroll
    for (int b = 0; b < 4; b++)
    #pragma unroll
    for (int cc = 0; cc < 4; cc++) acc[a][b][cc] = 0.f;

    load_chunk(sbase, Ah, Al, Bh, Bl, m0, n0, 0, bmap, tid);
    for (int k = 0; k < 16; k++) {
        int st = k & 1;
        if (k < 15) {
            load_chunk(sbase + (st^1)*STW*4, Ah, Al, Bh, Bl, m0, n0, k+1, bmap, tid);
            CPWAIT(1);
        } else {
            CPWAIT(0);
        }
        __syncthreads();
        compute_chunk(sbase + st*STW*4, acc, lane, wm, wn);
        __syncthreads();
    }

    #pragma unroll
    for (int mt = 0; mt < 4; mt++) {
        #pragma unroll
        for (int half = 0; half < 2; half++) {
            int m = m0 + wm*64 + mt*16 + (lane >> 2) + half*8;
            float rb = br1 ? (br1[m] + br2[m]) : 0.f;
            #pragma unroll
            for (int nt = 0; nt < 4; nt++) {
                int c = n0 + wn*32 + nt*8 + (lane & 3)*2;
                float v0 = acc[mt][nt][half*2+0] + rb;
                float v1 = acc[mt][nt][half*2+1] + rb;
                if (bcn) { v0 += bcn[c]; v1 += bcn[c+1]; }
                if (cmode) {
                    float* dst = C + ((size_t)(c >> 9)*G4 + m)*Bsz + (c & 511);
                    *(float2*)dst = make_float2(v0, v1);
                } else {
                    *(float2*)(C + (size_t)m*Ntot + c) = make_float2(v0, v1);
                }
            }
        }
    }
}

// ============ persistent LSTM recurrence ============
// grid (32,4): x -> 16 units (u0), y -> 128 batch (b0). Group barrier per y.
// SMEM: W[hl][16ck][64r][20w] = 163840B; H[3st][hl][128r][20w] = 61440B
#define PS_SMEM 225280
__device__ __forceinline__ int WOFFf(int hl,int ck,int r){ return (((hl)*16+(ck))*64 + (r))*20; }
__device__ __forceinline__ int HOFFf(int st,int hl,int r){ return 40960 + ((((st)*2+(hl))*128) + (r))*20; }

__global__ void reset_bar(){ int i = threadIdx.x; if (i < 4) { g_gen[i] = 0; g_cnt[i] = 0; } }

__global__ void __launch_bounds__(256,1)
lstm_persist(const float* __restrict__ xg,
             const bf16* __restrict__ Wh, const bf16* __restrict__ Wl,
             bf16* __restrict__ h0h, bf16* __restrict__ h0l,
             bf16* __restrict__ h1h, bf16* __restrict__ h1l,
             float* __restrict__ cst, bf16* __restrict__ seqh, bf16* __restrict__ seql)
{
    extern __shared__ uint32_t sm[];
    uint32_t sb = smem_u32(sm);
    int tid = threadIdx.x, lane = tid & 31, w = tid >> 5;
    int laneR = lane >> 2, laneC = lane & 3;
    int u0 = blockIdx.x * 16;
    int b0 = blockIdx.y * 128;
    int gid = blockIdx.y;
    unsigned nGrp = gridDim.x;

    int laneA_r = lane & 15;
    int laneA_c = (lane >> 4) * 4;
    int laneB_r = (lane & 7) + ((lane >> 4) << 3);
    int laneB_c = ((lane >> 3) & 1) * 4;

    // ---- persistent W tile: rows n = g*16+ul -> Whh row g*512 + u0+ul ----
    for (int i = tid; i < 8192; i += 256) {
        int hl = i >> 12, j = i & 4095;
        int r = j >> 6, q = j & 63;
        int ck = q >> 2, wq = q & 3;
        int g = r >> 4, ul = r & 15;
        const bf16* src = (hl ? Wl : Wh) + ((size_t)(g*Hsz + u0 + ul))*Hsz + q*8;
        CP16(sb + (WOFFf(hl,ck,r) + wq*4)*4, src);
    }
    CPCOMMIT(); CPWAIT(0);
    __syncthreads();

    bf16* hh[2] = {h0h, h1h};
    bf16* hl2[2] = {h0l, h1l};

    for (int t = 0; t < Tsz; t++) {
        const bf16* Hh = hh[t & 1];
        const bf16* Hl = hl2[t & 1];
        bf16* Nh = hh[(t+1) & 1];
        bf16* Nl = hl2[(t+1) & 1];

        // prefetch xg (independent of h)
        float xv[2][16];
        {
            const float* xgt = xg + (size_t)t*G4*Bsz;
            #pragma unroll
            for (int half = 0; half < 2; half++) {
                int b = b0 + w*16 + laneR + half*8;
                #pragma unroll
                for (int uh = 0; uh < 2; uh++)
                #pragma unroll
                for (int du = 0; du < 2; du++) {
                    int u = u0 + laneC*2 + uh*8 + du;
                    #pragma unroll
                    for (int g = 0; g < 4; g++)
                        xv[half][uh*8 + du*4 + g] = xgt[((size_t)(g*Hsz + u))*Bsz + b];
                }
            }
        }

        float acc[8][4];
        #pragma unroll
        for (int i = 0; i < 8; i++)
        #pragma unroll
        for (int j = 0; j < 4; j++) acc[i][j] = 0.f;

        auto ldh = [&](int ck, int st){
            #pragma unroll
            for (int i = tid; i < 512; i += 256) {
                int r = i >> 2, q = i & 3;
                size_t src = (size_t)(b0 + r)*Hsz + ck*32 + q*8;
                CP16(sb + (HOFFf(st,0,r) + q*4)*4, Hh + src);
                CP16(sb + (HOFFf(st,1,r) + q*4)*4, Hl + src);
            }
            CPCOMMIT();
        };

        ldh(0, 0);
        int st = 0, nst = 1;
        for (int ck = 0; ck < 16; ck++) {
            if (ck < 15) { ldh(ck+1, nst); CPWAIT(1); } else { CPWAIT(0); }
            __syncthreads();
            // compute chunk ck from stage st
            #pragma unroll
            for (int ks = 0; ks < 2; ks++) {
                int kw = ks*8;
                uint32_t ah[4], al[4], bh[4][4], bl[4][4];
                uint32_t aw = (uint32_t)(w*16 + laneA_r)*20 + kw + laneA_c;
                LDSM4(ah, sb + (HOFFf(st,0,0) + aw)*4);
                LDSM4(al, sb + (HOFFf(st,1,0) + aw)*4);
                #pragma unroll
                for (int np = 0; np < 4; np++) {
                    uint32_t bw = (uint32_t)(np*16 + laneB_r)*20 + kw + laneB_c;
                    LDSM4(bh[np], sb + (WOFFf(0,ck,0) + bw)*4);
                    LDSM4(bl[np], sb + (WOFFf(1,ck,0) + bw)*4);
                }
                #pragma unroll
                for (int nt = 0; nt < 8; nt++) {
                    const uint32_t* BH = &bh[nt>>1][(nt&1)*2];
                    const uint32_t* BL = &bl[nt>>1][(nt&1)*2];
                    mma16816(acc[nt], ah, BH);
                    mma16816(acc[nt], ah, BL);
                    mma16816(acc[nt], al, BH);
                }
            }
            st = nst; nst = (nst + 1 == 3) ? 0 : nst + 1;
        }

        // epilogue
        #pragma unroll
        for (int half = 0; half < 2; half++) {
            int b = b0 + w*16 + laneR + half*8;
            #pragma unroll
            for (int uh = 0; uh < 2; uh++) {
                float cn[2], hn[2];
                #pragma unroll
                for (int du = 0; du < 2; du++) {
                    int q = half*2 + du;
                    float gi = acc[0*2+uh][q] + xv[half][uh*8+du*4+0];
                    float gf = acc[1*2+uh][q] + xv[half][uh*8+du*4+1];
                    float gg = acc[2*2+uh][q] + xv[half][uh*8+du*4+2];
                    float go = acc[3*2+uh][q] + xv[half][uh*8+du*4+3];
                    float is = 1.f/(1.f + __expf(-gi));
                    float fs = 1.f/(1.f + __expf(-gf));
                    float os = 1.f/(1.f + __expf(-go));
                    float gt = tanhf(gg);
                    int u = u0 + laneC*2 + uh*8 + du;
                    float co = cst[(size_t)b*Hsz + u];
                    cn[du] = fs*co + is*gt;
                    hn[du] = os*tanhf(cn[du]);
                }
                int u2 = u0 + laneC*2 + uh*8;
                size_t so = (size_t)b*Hsz + u2;
                *(float2*)(cst + so) = make_float2(cn[0], cn[1]);
                bf16 hb0 = __float2bfloat16_rn(hn[0]);
                bf16 hb1 = __float2bfloat16_rn(hn[1]);
                __nv_bfloat162 hp; hp.x = hb0; hp.y = hb1;
                __nv_bfloat162 lp;
                lp.x = __float2bfloat16_rn(hn[0] - __bfloat162float(hb0));
                lp.y = __float2bfloat16_rn(hn[1] - __bfloat162float(hb1));
                *(__nv_bfloat162*)(Nh + so) = hp;
                *(__nv_bfloat162*)(Nl + so) = lp;
                size_t qo = ((size_t)b*Tsz + t)*Hsz + u2;
                *(__nv_bfloat162*)(seqh + qo) = hp;
                *(__nv_bfloat162*)(seql + qo) = lp;
            }
        }

        // ---- per-group grid barrier (32 CTAs sharing b0) ----
        if (t < Tsz - 1) {
            __threadfence();
            __syncthreads();
            if (tid == 0) {
                unsigned target = (unsigned)(t + 1);
                if (atomicAdd(&g_cnt[gid], 1u) == nGrp - 1u) {
                    atomicExch(&g_cnt[gid], 0u);
                    __threadfence();
                    atomicAdd(&g_gen[gid], 1u);
                } else {
                    unsigned v;
                    do { asm volatile("ld.acquire.gpu.global.u32 %0, [%1];" : "=r"(v) : "l"(&g_gen[gid])); }
                    while (v < target);
                }
            }
            __syncthreads();
            __threadfence();
        }
    }
}

// ---------------- small kernels ----------------
__global__ void split_kernel(const float* __restrict__ s, bf16* __restrict__ h,
                             bf16* __restrict__ l, int n4){
    int i = blockIdx.x*blockDim.x + threadIdx.x;
    if (i < n4) {
        float4 v = ((const float4*)s)[i];
        bf16 h0 = __float2bfloat16_rn(v.x), h1 = __float2bfloat16_rn(v.y);
        bf16 h2 = __float2bfloat16_rn(v.z), h3 = __float2bfloat16_rn(v.w);
        __align__(8) bf16 hv[4] = {h0,h1,h2,h3};
        __align__(8) bf16 lv[4] = {
            __float2bfloat16_rn(v.x - __bfloat162float(h0)),
            __float2bfloat16_rn(v.y - __bfloat162float(h1)),
            __float2bfloat16_rn(v.z - __bfloat162float(h2)),
            __float2bfloat16_rn(v.w - __bfloat162float(h3)) };
        ((uint2*)h)[i] = *(uint2*)hv;
        ((uint2*)l)[i] = *(uint2*)lv;
    }
}
__global__ void embed_kernel(const int* __restrict__ x, const float* __restrict__ y,
                             const float* __restrict__ emb, const float* __restrict__ yW,
                             const float* __restrict__ yb, bf16* __restrict__ oh, bf16* __restrict__ ol){
    int bt = blockIdx.x;            // bt = t*512 + b
    int t = bt >> 9, b = bt & 511;
    int h4 = threadIdx.x;           // 128 threads x 4
    int tok = (t == 0) ? Vsz : x[b*Tsz + t - 1];
    float4 e = ((const float4*)(emb + (size_t)tok*Hsz))[h4];
    float4 wv = ((const float4*)yW)[h4];
    float4 bv = ((const float4*)yb)[h4];
    float yy = y[b];
    float v0 = e.x + yy*wv.x + bv.x, v1 = e.y + yy*wv.y + bv.y;
    float v2 = e.z + yy*wv.z + bv.z, v3 = e.w + yy*wv.w + bv.w;
    bf16 h0 = __float2bfloat16_rn(v0), h1 = __float2bfloat16_rn(v1);
    bf16 h2 = __float2bfloat16_rn(v2), h3 = __float2bfloat16_rn(v3);
    __align__(8) bf16 hv[4] = {h0,h1,h2,h3};
    __align__(8) bf16 lv[4] = {
        __float2bfloat16_rn(v0 - __bfloat162float(h0)),
        __float2bfloat16_rn(v1 - __bfloat162float(h1)),
        __float2bfloat16_rn(v2 - __bfloat162float(h2)),
        __float2bfloat16_rn(v3 - __bfloat162float(h3)) };
    ((uint2*)(oh + (size_t)bt*Hsz))[h4] = *(uint2*)hv;
    ((uint2*)(ol + (size_t)bt*Hsz))[h4] = *(uint2*)lv;
}
__global__ void zero_kernel(bf16* hb, bf16* lb, float* c){
    int i = blockIdx.x*blockDim.x + threadIdx.x;
    if (i < Bsz*Hsz) { c[i] = 0.f; hb[i] = __float2bfloat16(0.f); lb[i] = __float2bfloat16(0.f); }
}

// ---------------- launch ----------------
extern "C" void kernel_launch(void* const* d_in, const int* in_sizes, int n_in,
                              void* d_out, int out_size)
{
    const int*   x    = (const int*)  d_in[0];
    const float* y    = (const float*)d_in[1];
    const float* emb  = (const float*)d_in[2];
    const float* yW   = (const float*)d_in[3];
    const float* yb   = (const float*)d_in[4];
    const float* Wih  = (const float*)d_in[5];
    const float* Whh  = (const float*)d_in[6];
    const float* bih  = (const float*)d_in[7];
    const float* bhh  = (const float*)d_in[8];
    const float* decW = (const float*)d_in[9];
    const float* decb = (const float*)d_in[10];
    float* out = (float*)d_out;

    bf16 *inp_h, *inp_l, *seq_h, *seq_l, *Wih_h, *Wih_l, *Whh_h, *Whh_l, *dW_h, *dW_l;
    bf16 *h0h, *h0l, *h1h, *h1l;
    float *xgT, *c;
    cudaGetSymbolAddress((void**)&inp_h, g_inp_h);
    cudaGetSymbolAddress((void**)&inp_l, g_inp_l);
    cudaGetSymbolAddress((void**)&seq_h, g_seq_h);
    cudaGetSymbolAddress((void**)&seq_l, g_seq_l);
    cudaGetSymbolAddress((void**)&xgT,   g_xgT);
    cudaGetSymbolAddress((void**)&h0h,   g_h0h);
    cudaGetSymbolAddress((void**)&h0l,   g_h0l);
    cudaGetSymbolAddress((void**)&h1h,   g_h1h);
    cudaGetSymbolAddress((void**)&h1l,   g_h1l);
    cudaGetSymbolAddress((void**)&c,     g_c);
    cudaGetSymbolAddress((void**)&Wih_h, g_Wih_h);
    cudaGetSymbolAddress((void**)&Wih_l, g_Wih_l);
    cudaGetSymbolAddress((void**)&Whh_h, g_Whh_h);
    cudaGetSymbolAddress((void**)&Whh_l, g_Whh_l);
    cudaGetSymbolAddress((void**)&dW_h,  g_dW_h);
    cudaGetSymbolAddress((void**)&dW_l,  g_dW_l);

    cudaFuncSetAttribute(gemm_mma, cudaFuncAttributeMaxDynamicSharedMemorySize, SMEMB);
    cudaFuncSetAttribute(lstm_persist, cudaFuncAttributeMaxDynamicSharedMemorySize, PS_SMEM);

    const int nW4 = 2*G4*Hsz/4;
    split_kernel<<<(nW4+255)/256, 256>>>(Wih, Wih_h, Wih_l, nW4);
    split_kernel<<<(nW4+255)/256, 256>>>(Whh, Whh_h, Whh_l, nW4);
    split_kernel<<<(Vsz*Hsz/4+255)/256, 256>>>(decW, dW_h, dW_l, Vsz*Hsz/4);
    embed_kernel<<<NBT, 128>>>(x, y, emb, yW, yb, inp_h, inp_l);

    for (int l = 0; l < 2; l++) {
        const bf16* Bh = l ? seq_h : inp_h;
        const bf16* Bl = l ? seq_l : inp_l;
        // xgT[t][n][b] = Wih[n]·inp[t,b] + bih[n] + bhh[n]
        gemm_mma<<<dim3(G4/128, NBT/128), 256, SMEMB>>>(
            Wih_h + (size_t)l*G4*Hsz, Wih_l + (size_t)l*G4*Hsz,
            Bh, Bl, bih + l*G4, bhh + l*G4, nullptr, xgT, NBT, l ? 1 : 0, 1, 1);

        zero_kernel<<<(Bsz*Hsz+255)/256, 256>>>(h0h, h0l, c);
        reset_bar<<<1, 4>>>();

        lstm_persist<<<dim3(Hsz/16, Bsz/128), 256, PS_SMEM>>>(
            xgT, Whh_h + (size_t)l*G4*Hsz, Whh_l + (size_t)l*G4*Hsz,
            h0h, h0l, h1h, h1l, c, seq_h, seq_l);
    }

    // decoder: out[(b*T+t)][v] = seq·decW^T + decb
    gemm_mma<<<dim3(Vsz/128, NBT/128), 256, SMEMB>>>(
        seq_h, seq_l, dW_h, dW_l, nullptr, nullptr, decb, out, Vsz, 0, 0, 0);
}

// round 7
// speedup vs baseline: 5.4679x; 1.9341x over previous
#include <cuda_runtime.h>
#include <cuda_fp16.h>
#include <stdint.h>
#include <math.h>

#define Bsz 512
#define Tsz 128
#define Hsz 512
#define Vsz 512
#define NBT 65536
#define G4  2048

// ---------------- device scratch ----------------
__device__ __align__(128) __half g_inp[(size_t)NBT*Hsz];
__device__ __align__(128) __half g_seq[(size_t)NBT*Hsz];
__device__ __align__(128) float  g_xgT[(size_t)Tsz*G4*Bsz];   // [t][n][b]
__device__ __align__(128) __half g_h0[Bsz*Hsz], g_h1[Bsz*Hsz];
__device__ __align__(128) float  g_c[Bsz*Hsz];
__device__ __align__(128) __half g_Wih[2*(size_t)G4*Hsz];
__device__ __align__(128) __half g_Whh[2*(size_t)G4*Hsz];
__device__ __align__(128) __half g_dW[(size_t)Vsz*Hsz];
__device__ unsigned g_gen[4], g_cnt[4];

// ---------------- helpers ----------------
__device__ __forceinline__ uint32_t smem_u32(const void* p){
    uint32_t a; asm("{ .reg .u64 t; cvta.to.shared.u64 t, %1; cvt.u32.u64 %0, t; }" : "=r"(a) : "l"(p)); return a;
}
#define CP16(dst, src) asm volatile("cp.async.cg.shared.global [%0], [%1], 16;" :: "r"(dst), "l"(src))
#define CPCOMMIT()     asm volatile("cp.async.commit_group;" ::: "memory")
#define CPWAIT(n)      asm volatile("cp.async.wait_group %0;" :: "n"(n) : "memory")
#define LDSM4(r, a) asm volatile("ldmatrix.sync.aligned.m8n8.x4.shared.b16 {%0,%1,%2,%3}, [%4];" \
    : "=r"((r)[0]),"=r"((r)[1]),"=r"((r)[2]),"=r"((r)[3]) : "r"(a))

__device__ __forceinline__ void mma16816(float* d, const uint32_t* a, const uint32_t* b){
    asm volatile("mma.sync.aligned.m16n8k16.row.col.f32.f16.f16.f32 "
        "{%0,%1,%2,%3}, {%4,%5,%6,%7}, {%8,%9}, {%0,%1,%2,%3};"
        : "+f"(d[0]), "+f"(d[1]), "+f"(d[2]), "+f"(d[3])
        : "r"(a[0]), "r"(a[1]), "r"(a[2]), "r"(a[3]), "r"(b[0]), "r"(b[1]));
}

// ============ generic FF GEMM (fp16 operands, fp32 accum) ============
// chunk: 128 rows x 32 k fp16, row padded to 20 words. A then B.
#define CHW 2560
#define STW 5120
#define SMEMB 61440   // 3 stages

__device__ __forceinline__ void load_chunk(uint32_t sbase,
    const __half* __restrict__ A, const __half* __restrict__ B,
    int m0, int n0, int ck, int bmap, int tid)
{
    #pragma unroll
    for (int i = tid; i < 512; i += 256) {
        int r = i >> 2, q = i & 3;
        CP16(sbase + (r*20 + q*4)*4, A + (size_t)(m0 + r)*Hsz + ck*32 + q*8);
    }
    #pragma unroll
    for (int i = tid; i < 512; i += 256) {
        int r = i >> 2, q = i & 3;
        int brow;
        if (bmap == 0)      brow = n0 + r;
        else                { int c = n0 + r; brow = (c & 511)*Tsz + (c >> 9); }
        CP16(sbase + (CHW + r*20 + q*4)*4, B + (size_t)brow*Hsz + ck*32 + q*8);
    }
    CPCOMMIT();
}

__device__ __forceinline__ void compute_chunk(uint32_t stg,
    float acc[4][4][4], int lane, int wm, int wn)
{
    int laneA_r = lane & 15;
    int laneA_c = (lane >> 4) * 4;
    int laneB_r = (lane & 7) + ((lane >> 4) << 3);
    int laneB_c = ((lane >> 3) & 1) * 4;
    #pragma unroll
    for (int ks = 0; ks < 2; ks++) {
        int kw = ks*8;
        uint32_t ah[4][4], bh[2][4];
        #pragma unroll
        for (int mt = 0; mt < 4; mt++) {
            uint32_t aw = (uint32_t)(wm*64 + mt*16 + laneA_r)*20 + kw + laneA_c;
            LDSM4(ah[mt], stg + aw*4);
        }
        #pragma unroll
        for (int np = 0; np < 2; np++) {
            uint32_t bw = (uint32_t)(wn*32 + np*16 + laneB_r)*20 + kw + laneB_c;
            LDSM4(bh[np], stg + (CHW + bw)*4);
        }
        #pragma unroll
        for (int mt = 0; mt < 4; mt++)
        #pragma unroll
        for (int nt = 0; nt < 4; nt++)
            mma16816(acc[mt][nt], ah[mt], &bh[nt>>1][(nt&1)*2]);
    }
}

__global__ void __launch_bounds__(256)
gemm_mma(const __half* __restrict__ A, const __half* __restrict__ B,
         const float* __restrict__ br1, const float* __restrict__ br2,
         const float* __restrict__ bcn, float* __restrict__ C,
         int Ntot, int bmap, int mx, int cmode)
{
    extern __shared__ uint32_t sm[];
    uint32_t sbase = smem_u32(sm);
    int tid = threadIdx.x, lane = tid & 31, wid = tid >> 5;
    int wm = wid >> 2, wn = wid & 3;
    int bm = mx ? blockIdx.x : blockIdx.y;
    int bn = mx ? blockIdx.y : blockIdx.x;
    int m0 = bm*128, n0 = bn*128;

    float acc[4][4][4];
    #pragma unroll
    for (int a = 0; a < 4; a++)
    #pragma unroll
    for (int b = 0; b < 4; b++)
    #pragma unroll
    for (int cc = 0; cc < 4; cc++) acc[a][b][cc] = 0.f;

    load_chunk(sbase, A, B, m0, n0, 0, bmap, tid);
    int st = 0, nst = 1;
    for (int k = 0; k < 16; k++) {
        if (k < 15) {
            load_chunk(sbase + nst*STW*4, A, B, m0, n0, k+1, bmap, tid);
            CPWAIT(1);
        } else {
            CPWAIT(0);
        }
        __syncthreads();
        compute_chunk(sbase + st*STW*4, acc, lane, wm, wn);
        st = nst; nst = (nst + 1 == 3) ? 0 : nst + 1;
    }

    #pragma unroll
    for (int mt = 0; mt < 4; mt++) {
        #pragma unroll
        for (int half = 0; half < 2; half++) {
            int m = m0 + wm*64 + mt*16 + (lane >> 2) + half*8;
            float rb = br1 ? (br1[m] + br2[m]) : 0.f;
            #pragma unroll
            for (int nt = 0; nt < 4; nt++) {
                int c = n0 + wn*32 + nt*8 + (lane & 3)*2;
                float v0 = acc[mt][nt][half*2+0] + rb;
                float v1 = acc[mt][nt][half*2+1] + rb;
                if (bcn) { v0 += bcn[c]; v1 += bcn[c+1]; }
                if (cmode) {
                    float* dst = C + ((size_t)(c >> 9)*G4 + m)*Bsz + (c & 511);
                    *(float2*)dst = make_float2(v0, v1);
                } else {
                    *(float2*)(C + (size_t)m*Ntot + c) = make_float2(v0, v1);
                }
            }
        }
    }
}

// ============ persistent LSTM recurrence (fp16) ============
// grid (32,4): x -> 16 units (u0), y -> 128 batch (b0). Group barrier per y.
// BK=64, 8 chunks, 3-stage h pipeline, row pad 36 words.
// W: 8ck x 64r x 36w = 18432 words (73728B); H: 3st x 128r x 36w = 13824 w (55296B)
#define PS_SMEM 129536
__device__ __forceinline__ int WOFFf(int ck,int r){ return (ck*64 + r)*36; }
__device__ __forceinline__ int HOFFf(int st,int r){ return 18432 + (st*128 + r)*36; }

__global__ void reset_bar(){ int i = threadIdx.x; if (i < 4) { g_gen[i] = 0; g_cnt[i] = 0; } }

__global__ void __launch_bounds__(256,1)
lstm_persist(const float* __restrict__ xg, const __half* __restrict__ W,
             __half* __restrict__ h0, __half* __restrict__ h1,
             float* __restrict__ cst, __half* __restrict__ seq)
{
    extern __shared__ uint32_t sm[];
    uint32_t sb = smem_u32(sm);
    int tid = threadIdx.x, lane = tid & 31, w = tid >> 5;
    int laneR = lane >> 2, laneC = lane & 3;
    int u0 = blockIdx.x * 16;
    int b0 = blockIdx.y * 128;
    int gid = blockIdx.y;
    unsigned nGrp = gridDim.x;

    int laneA_r = lane & 15;
    int laneA_c = (lane >> 4) * 4;
    int laneB_r = (lane & 7) + ((lane >> 4) << 3);
    int laneB_c = ((lane >> 3) & 1) * 4;

    // ---- persistent W tile: rows n = g*16+ul -> Whh row g*512 + u0+ul ----
    for (int i = tid; i < 4096; i += 256) {
        int ck = i >> 9, rem = i & 511;
        int r = rem >> 3, q = rem & 7;
        int g = r >> 4, ul = r & 15;
        CP16(sb + (WOFFf(ck,r) + q*4)*4,
             W + ((size_t)(g*Hsz + u0 + ul))*Hsz + ck*64 + q*8);
    }
    CPCOMMIT(); CPWAIT(0);
    __syncthreads();

    __half* hb[2] = {h0, h1};

    for (int t = 0; t < Tsz; t++) {
        const __half* Hc = hb[t & 1];
        __half* Nx = hb[(t+1) & 1];

        // prefetch xg (independent of h)
        float xv[2][16];
        {
            const float* xgt = xg + (size_t)t*G4*Bsz;
            #pragma unroll
            for (int half = 0; half < 2; half++) {
                int b = b0 + w*16 + laneR + half*8;
                #pragma unroll
                for (int uh = 0; uh < 2; uh++)
                #pragma unroll
                for (int du = 0; du < 2; du++) {
                    int u = u0 + laneC*2 + uh*8 + du;
                    #pragma unroll
                    for (int g = 0; g < 4; g++)
                        xv[half][uh*8 + du*4 + g] = xgt[((size_t)(g*Hsz + u))*Bsz + b];
                }
            }
        }

        float acc[8][4];
        #pragma unroll
        for (int i = 0; i < 8; i++)
        #pragma unroll
        for (int j = 0; j < 4; j++) acc[i][j] = 0.f;

        auto ldh = [&](int ck, int st){
            #pragma unroll
            for (int i = tid; i < 1024; i += 256) {
                int r = i >> 3, q = i & 7;
                CP16(sb + (HOFFf(st,r) + q*4)*4, Hc + (size_t)(b0 + r)*Hsz + ck*64 + q*8);
            }
            CPCOMMIT();
        };

        ldh(0, 0);
        int st = 0, nst = 1;
        for (int ck = 0; ck < 8; ck++) {
            if (ck < 7) { ldh(ck+1, nst); CPWAIT(1); } else { CPWAIT(0); }
            __syncthreads();
            #pragma unroll
            for (int ks = 0; ks < 4; ks++) {
                int kw = ks*8;
                uint32_t ah[4], bh[4][4];
                uint32_t aw = (uint32_t)(HOFFf(st, w*16 + laneA_r)) + kw + laneA_c;
                LDSM4(ah, sb + aw*4);
                #pragma unroll
                for (int np = 0; np < 4; np++) {
                    uint32_t bw = (uint32_t)(WOFFf(ck, np*16 + laneB_r)) + kw + laneB_c;
                    LDSM4(bh[np], sb + bw*4);
                }
                #pragma unroll
                for (int nt = 0; nt < 8; nt++)
                    mma16816(acc[nt], ah, &bh[nt>>1][(nt&1)*2]);
            }
            st = nst; nst = (nst + 1 == 3) ? 0 : nst + 1;
        }

        // epilogue: gates + state update
        #pragma unroll
        for (int half = 0; half < 2; half++) {
            int b = b0 + w*16 + laneR + half*8;
            #pragma unroll
            for (int uh = 0; uh < 2; uh++) {
                float cn[2], hn[2];
                #pragma unroll
                for (int du = 0; du < 2; du++) {
                    int q = half*2 + du;
                    float gi = acc[0*2+uh][q] + xv[half][uh*8+du*4+0];
                    float gf = acc[1*2+uh][q] + xv[half][uh*8+du*4+1];
                    float gg = acc[2*2+uh][q] + xv[half][uh*8+du*4+2];
                    float go = acc[3*2+uh][q] + xv[half][uh*8+du*4+3];
                    float is = 1.f/(1.f + __expf(-gi));
                    float fs = 1.f/(1.f + __expf(-gf));
                    float os = 1.f/(1.f + __expf(-go));
                    float gt = tanhf(gg);
                    int u = u0 + laneC*2 + uh*8 + du;
                    float co = cst[(size_t)b*Hsz + u];
                    cn[du] = fs*co + is*gt;
                    hn[du] = os*tanhf(cn[du]);
                }
                int u2 = u0 + laneC*2 + uh*8;
                size_t so = (size_t)b*Hsz + u2;
                *(float2*)(cst + so) = make_float2(cn[0], cn[1]);
                __half2 hp;
                hp.x = __float2half_rn(hn[0]);
                hp.y = __float2half_rn(hn[1]);
                *(__half2*)(Nx + so) = hp;
                *(__half2*)(seq + ((size_t)b*Tsz + t)*Hsz + u2) = hp;
            }
        }

        // ---- per-group grid barrier (32 CTAs sharing b0) ----
        if (t < Tsz - 1) {
            __threadfence();
            __syncthreads();
            if (tid == 0) {
                unsigned target = (unsigned)(t + 1);
                if (atomicAdd(&g_cnt[gid], 1u) == nGrp - 1u) {
                    atomicExch(&g_cnt[gid], 0u);
                    __threadfence();
                    atomicAdd(&g_gen[gid], 1u);
                } else {
                    unsigned v;
                    do { asm volatile("ld.acquire.gpu.global.u32 %0, [%1];" : "=r"(v) : "l"(&g_gen[gid])); }
                    while (v < target);
                }
            }
            __syncthreads();
            __threadfence();
        }
    }
}

// ---------------- small kernels ----------------
__global__ void conv_kernel(const float* __restrict__ s, __half* __restrict__ h, int n4){
    int i = blockIdx.x*blockDim.x + threadIdx.x;
    if (i < n4) {
        float4 v = ((const float4*)s)[i];
        __half2 a, b;
        a.x = __float2half_rn(v.x); a.y = __float2half_rn(v.y);
        b.x = __float2half_rn(v.z); b.y = __float2half_rn(v.w);
        ((__half2*)h)[i*2]   = a;
        ((__half2*)h)[i*2+1] = b;
    }
}
__global__ void embed_kernel(const int* __restrict__ x, const float* __restrict__ y,
                             const float* __restrict__ emb, const float* __restrict__ yW,
                             const float* __restrict__ yb, __half* __restrict__ o){
    int bt = blockIdx.x;            // bt = t*512 + b
    int t = bt >> 9, b = bt & 511;
    int h4 = threadIdx.x;           // 128 threads x 4 elems
    int tok = (t == 0) ? Vsz : x[b*Tsz + t - 1];
    float4 e = ((const float4*)(emb + (size_t)tok*Hsz))[h4];
    float4 wv = ((const float4*)yW)[h4];
    float4 bv = ((const float4*)yb)[h4];
    float yy = y[b];
    __half2 a, c;
    a.x = __float2half_rn(e.x + yy*wv.x + bv.x);
    a.y = __float2half_rn(e.y + yy*wv.y + bv.y);
    c.x = __float2half_rn(e.z + yy*wv.z + bv.z);
    c.y = __float2half_rn(e.w + yy*wv.w + bv.w);
    ((__half2*)(o + (size_t)bt*Hsz))[h4*2]   = a;
    ((__half2*)(o + (size_t)bt*Hsz))[h4*2+1] = c;
}
__global__ void zero_kernel(__half* hb, float* c){
    int i = blockIdx.x*blockDim.x + threadIdx.x;
    if (i < Bsz*Hsz) { c[i] = 0.f; hb[i] = __float2half(0.f); }
}

// ---------------- launch ----------------
extern "C" void kernel_launch(void* const* d_in, const int* in_sizes, int n_in,
                              void* d_out, int out_size)
{
    const int*   x    = (const int*)  d_in[0];
    const float* y    = (const float*)d_in[1];
    const float* emb  = (const float*)d_in[2];
    const float* yW   = (const float*)d_in[3];
    const float* yb   = (const float*)d_in[4];
    const float* Wih  = (const float*)d_in[5];
    const float* Whh  = (const float*)d_in[6];
    const float* bih  = (const float*)d_in[7];
    const float* bhh  = (const float*)d_in[8];
    const float* decW = (const float*)d_in[9];
    const float* decb = (const float*)d_in[10];
    float* out = (float*)d_out;

    __half *inp, *seq, *Wih_c, *Whh_c, *dW_c, *h0, *h1;
    float *xgT, *c;
    cudaGetSymbolAddress((void**)&inp,   g_inp);
    cudaGetSymbolAddress((void**)&seq,   g_seq);
    cudaGetSymbolAddress((void**)&xgT,   g_xgT);
    cudaGetSymbolAddress((void**)&h0,    g_h0);
    cudaGetSymbolAddress((void**)&h1,    g_h1);
    cudaGetSymbolAddress((void**)&c,     g_c);
    cudaGetSymbolAddress((void**)&Wih_c, g_Wih);
    cudaGetSymbolAddress((void**)&Whh_c, g_Whh);
    cudaGetSymbolAddress((void**)&dW_c,  g_dW);

    cudaFuncSetAttribute(gemm_mma, cudaFuncAttributeMaxDynamicSharedMemorySize, SMEMB);
    cudaFuncSetAttribute(lstm_persist, cudaFuncAttributeMaxDynamicSharedMemorySize, PS_SMEM);

    const int nW4 = 2*G4*Hsz/4;
    conv_kernel<<<(nW4+255)/256, 256>>>(Wih, Wih_c, nW4);
    conv_kernel<<<(nW4+255)/256, 256>>>(Whh, Whh_c, nW4);
    conv_kernel<<<(Vsz*Hsz/4+255)/256, 256>>>(decW, dW_c, Vsz*Hsz/4);
    embed_kernel<<<NBT, 128>>>(x, y, emb, yW, yb, inp);

    for (int l = 0; l < 2; l++) {
        const __half* Bmat = l ? seq : inp;
        // xgT[t][n][b] = Wih[n]·inp[t,b] + bih[n] + bhh[n]
        gemm_mma<<<dim3(G4/128, NBT/128), 256, SMEMB>>>(
            Wih_c + (size_t)l*G4*Hsz, Bmat,
            bih + l*G4, bhh + l*G4, nullptr, xgT, NBT, l ? 1 : 0, 1, 1);

        zero_kernel<<<(Bsz*Hsz+255)/256, 256>>>(h0, c);
        reset_bar<<<1, 4>>>();

        lstm_persist<<<dim3(Hsz/16, Bsz/128), 256, PS_SMEM>>>(
            xgT, Whh_c + (size_t)l*G4*Hsz, h0, h1, c, seq);
    }

    // decoder: out[(b*T+t)][v] = seq·decW^T + decb
    gemm_mma<<<dim3(Vsz/128, NBT/128), 256, SMEMB>>>(
        seq, dW_c, nullptr, nullptr, decb, out, Vsz, 0, 0, 0);
}